// round 4
// baseline (speedup 1.0000x reference)
#include <cuda_runtime.h>
#include <cfloat>
#include <cmath>

// Problem constants
constexpr int B_ = 2;
constexpr int S_ = 2048;
constexpr int E_ = 2048;
constexpr int H_ = 16;
constexpr int D_ = 128;
constexpr int M_ = B_ * S_;   // 4096 rows for all GEMMs

// Scratch (static device globals: allowed; no dynamic allocation)
__device__ float g_Q[(size_t)B_ * S_ * E_];
__device__ float g_K[(size_t)B_ * S_ * E_];
__device__ float g_V[(size_t)B_ * S_ * E_];
__device__ float g_ctx[(size_t)B_ * S_ * E_];

// ---------------------------------------------------------------------------
// SGEMM: C[M,N] = A[M,K] @ W[K,N] (+ bias). 128x128 block tile, BK=16,
// 256 threads, 8x8 register microtile. M=4096, N=K=2048 (all divisible).
// ---------------------------------------------------------------------------
__device__ __forceinline__ void sgemm_128x128(
    const float* __restrict__ A, const float* __restrict__ W,
    float* __restrict__ C, const float* __restrict__ bias)
{
    constexpr int N = E_;
    constexpr int K = E_;
    __shared__ float As[16][132];   // transposed A tile, padded
    __shared__ float Bs[16][128];

    const int tid = threadIdx.x;
    const int tx = tid & 15;        // 0..15 -> 8 output cols each
    const int ty = tid >> 4;        // 0..15 -> 8 output rows each
    const int bm0 = blockIdx.y * 128;
    const int bn0 = blockIdx.x * 128;

    float acc[8][8];
#pragma unroll
    for (int i = 0; i < 8; i++)
#pragma unroll
        for (int j = 0; j < 8; j++) acc[i][j] = 0.f;

    for (int kt = 0; kt < K; kt += 16) {
        // Load A tile 128x16 (transposed into As)
#pragma unroll
        for (int i = 0; i < 2; i++) {
            int idx = tid + i * 256;             // 0..511
            int r   = idx >> 2;                  // 0..127
            int c4  = (idx & 3) << 2;            // 0,4,8,12
            float4 v = *(const float4*)(A + (size_t)(bm0 + r) * K + kt + c4);
            As[c4 + 0][r] = v.x;
            As[c4 + 1][r] = v.y;
            As[c4 + 2][r] = v.z;
            As[c4 + 3][r] = v.w;
        }
        // Load W tile 16x128
#pragma unroll
        for (int i = 0; i < 2; i++) {
            int idx = tid + i * 256;             // 0..511
            int r   = idx >> 5;                  // 0..15
            int c4  = (idx & 31) << 2;           // 0..124
            *(float4*)&Bs[r][c4] =
                *(const float4*)(W + (size_t)(kt + r) * N + bn0 + c4);
        }
        __syncthreads();

#pragma unroll
        for (int k = 0; k < 16; k++) {
            float a[8], b[8];
            *(float4*)&a[0] = *(float4*)&As[k][ty * 8];
            *(float4*)&a[4] = *(float4*)&As[k][ty * 8 + 4];
            *(float4*)&b[0] = *(float4*)&Bs[k][tx * 8];
            *(float4*)&b[4] = *(float4*)&Bs[k][tx * 8 + 4];
#pragma unroll
            for (int i = 0; i < 8; i++)
#pragma unroll
                for (int j = 0; j < 8; j++)
                    acc[i][j] += a[i] * b[j];
        }
        __syncthreads();
    }

    // Epilogue
    float bv[8];
#pragma unroll
    for (int j = 0; j < 8; j++)
        bv[j] = bias ? bias[bn0 + tx * 8 + j] : 0.f;

#pragma unroll
    for (int i = 0; i < 8; i++) {
        size_t row = (size_t)(bm0 + ty * 8 + i);
        float* Cr = C + row * N + bn0 + tx * 8;
        float4 r0, r1;
        r0.x = acc[i][0] + bv[0]; r0.y = acc[i][1] + bv[1];
        r0.z = acc[i][2] + bv[2]; r0.w = acc[i][3] + bv[3];
        r1.x = acc[i][4] + bv[4]; r1.y = acc[i][5] + bv[5];
        r1.z = acc[i][6] + bv[6]; r1.w = acc[i][7] + bv[7];
        *(float4*)(Cr)     = r0;
        *(float4*)(Cr + 4) = r1;
    }
}

__global__ void __launch_bounds__(256) qkv_kernel(
    const float* __restrict__ x,
    const float* __restrict__ Wq,
    const float* __restrict__ Wk,
    const float* __restrict__ Wv)
{
    const float* W = (blockIdx.z == 0) ? Wq : ((blockIdx.z == 1) ? Wk : Wv);
    float* C = (blockIdx.z == 0) ? g_Q : ((blockIdx.z == 1) ? g_K : g_V);
    sgemm_128x128(x, W, C, nullptr);
}

__global__ void __launch_bounds__(256) out_kernel(
    const float* __restrict__ Wo,
    const float* __restrict__ bo,
    float* __restrict__ out)
{
    sgemm_128x128(g_ctx, Wo, out, bo);
}

// ---------------------------------------------------------------------------
// Flash attention: 64x64 tiles, online softmax, causal + ALiBi.
// Grid (S/64, H, B), 128 threads.
// tr = tid>>3 (owns q-rows 4*tr..4*tr+3); tc = tid&7.
// ---------------------------------------------------------------------------
constexpr int SMEM_FLOATS = 2 * 64 * 129 + 64 * 65 + 3 * 64;  // 20864
constexpr int SMEM_BYTES  = SMEM_FLOATS * 4;                  // 83456

__device__ __forceinline__ void load_tile64x128(
    const float* __restrict__ gp, float* __restrict__ dst, int tid)
{
    // 64 rows x 128 cols, gmem row stride E_, smem row stride 129
    for (int idx = tid; idx < 64 * 32; idx += 128) {
        int r  = idx >> 5;
        int c4 = (idx & 31) << 2;
        float4 v = *(const float4*)(gp + (size_t)r * E_ + c4);
        float* d = dst + r * 129 + c4;
        d[0] = v.x; d[1] = v.y; d[2] = v.z; d[3] = v.w;
    }
}

__global__ void __launch_bounds__(128) attn_kernel()
{
    const int tid = threadIdx.x;
    const int qt  = blockIdx.x;
    const int h   = blockIdx.y;
    const int b   = blockIdx.z;
    const int q0  = qt * 64;
    const int tr  = tid >> 3;
    const int tc  = tid & 7;

    extern __shared__ float sm[];
    float* Qs  = sm;                       // [64][129]
    float* KVs = sm + 64 * 129;            // [64][129]
    float* Ssm = sm + 2 * 64 * 129;        // [64][65]
    float* msr = Ssm + 64 * 65;            // [64] running max
    float* lsr = msr + 64;                 // [64] running sum
    float* csr = lsr + 64;                 // [64] correction

    const float slope = exp2f(-0.5f * (float)(h + 1));
    const float inv_s = rsqrtf((float)D_);

    const float* Qp = g_Q + (((size_t)b * S_ + q0) * E_ + (size_t)h * D_);
    load_tile64x128(Qp, Qs, tid);

    if (tid < 64) { msr[tid] = -FLT_MAX; lsr[tid] = 0.f; }

    float o[4][16];
#pragma unroll
    for (int i = 0; i < 4; i++)
#pragma unroll
        for (int c = 0; c < 16; c++) o[i][c] = 0.f;

    __syncthreads();

    for (int kt = 0; kt <= qt; kt++) {
        const int k0 = kt * 64;
        const float* Kp = g_K + (((size_t)b * S_ + k0) * E_ + (size_t)h * D_);
        load_tile64x128(Kp, KVs, tid);
        __syncthreads();

        // --- Phase A: S = Q @ K^T (4x8 microtile) ---
        float acc[4][8];
#pragma unroll
        for (int i = 0; i < 4; i++)
#pragma unroll
            for (int j = 0; j < 8; j++) acc[i][j] = 0.f;

#pragma unroll 4
        for (int kk = 0; kk < 128; kk++) {
            float qv[4], kv[8];
#pragma unroll
            for (int i = 0; i < 4; i++) qv[i] = Qs[(4 * tr + i) * 129 + kk];
#pragma unroll
            for (int j = 0; j < 8; j++) kv[j] = KVs[(8 * tc + j) * 129 + kk];
#pragma unroll
            for (int i = 0; i < 4; i++)
#pragma unroll
                for (int j = 0; j < 8; j++)
                    acc[i][j] += qv[i] * kv[j];
        }

        // mask -> +alibi -> scale (same order as reference), write to Ssm
#pragma unroll
        for (int i = 0; i < 4; i++) {
            const int ig = q0 + 4 * tr + i;
#pragma unroll
            for (int j = 0; j < 8; j++) {
                const int jg = k0 + 8 * tc + j;
                float sv = acc[i][j];
                if (jg > ig) sv = -1e30f;
                sv = (sv + slope * (float)(jg - ig)) * inv_s;
                Ssm[(4 * tr + i) * 65 + 8 * tc + j] = sv;
            }
        }
        __syncthreads();

        // --- Online softmax: 2 threads per row ---
        {
            const int r = tid >> 1, p = tid & 1;
            float* row = Ssm + r * 65 + p * 32;
            float lm = -FLT_MAX;
#pragma unroll 8
            for (int j2 = 0; j2 < 32; j2++) lm = fmaxf(lm, row[j2]);
            lm = fmaxf(lm, __shfl_xor_sync(0xffffffffu, lm, 1));
            const float mo = msr[r];
            const float mn = fmaxf(mo, lm);
            const float cc = __expf(mo - mn);
            float s = 0.f;
#pragma unroll 8
            for (int j2 = 0; j2 < 32; j2++) {
                float pv = __expf(row[j2] - mn);
                row[j2] = pv;
                s += pv;
            }
            s += __shfl_xor_sync(0xffffffffu, s, 1);
            if (!p) {
                msr[r] = mn;
                lsr[r] = cc * lsr[r] + s;
                csr[r] = cc;
            }
        }

        // Load V into KVs (K reads finished before the previous sync)
        const float* Vp = g_V + (((size_t)b * S_ + k0) * E_ + (size_t)h * D_);
        load_tile64x128(Vp, KVs, tid);
        __syncthreads();

        // --- Phase B: O = c*O + P @ V (4x16 microtile, cols tc + 8*c) ---
        float cr[4];
#pragma unroll
        for (int i = 0; i < 4; i++) cr[i] = csr[4 * tr + i];
#pragma unroll
        for (int i = 0; i < 4; i++)
#pragma unroll
            for (int c = 0; c < 16; c++) o[i][c] *= cr[i];

#pragma unroll 2
        for (int j = 0; j < 64; j++) {
            float pv[4], vv[16];
#pragma unroll
            for (int i = 0; i < 4; i++) pv[i] = Ssm[(4 * tr + i) * 65 + j];
#pragma unroll
            for (int c = 0; c < 16; c++) vv[c] = KVs[j * 129 + tc + 8 * c];
#pragma unroll
            for (int i = 0; i < 4; i++)
#pragma unroll
                for (int c = 0; c < 16; c++)
                    o[i][c] += pv[i] * vv[c];
        }
        __syncthreads();   // protect KVs/Ssm before next iteration
    }

    // Final normalize and store: ctx[b][q][h][d]
    float* Op = g_ctx + (((size_t)b * S_ + q0) * E_ + (size_t)h * D_);
#pragma unroll
    for (int i = 0; i < 4; i++) {
        const float inv_l = 1.0f / lsr[4 * tr + i];
#pragma unroll
        for (int c = 0; c < 16; c++)
            Op[(size_t)(4 * tr + i) * E_ + tc + 8 * c] = o[i][c] * inv_l;
    }
}

// ---------------------------------------------------------------------------
// Launch: QKV GEMMs -> attention -> output GEMM. Graph-capturable:
// kernel launches only, no syncs, no allocation.
// ---------------------------------------------------------------------------
extern "C" void kernel_launch(void* const* d_in, const int* in_sizes, int n_in,
                              void* d_out, int out_size)
{
    const float* x  = (const float*)d_in[0];
    const float* Wq = (const float*)d_in[1];
    const float* Wk = (const float*)d_in[2];
    const float* Wv = (const float*)d_in[3];
    const float* Wo = (const float*)d_in[4];
    const float* bo = (const float*)d_in[5];
    float* out = (float*)d_out;

    (void)in_sizes; (void)n_in; (void)out_size;

    // Fused QKV projections: z selects Wq/Wk/Wv -> g_Q/g_K/g_V
    dim3 gq(E_ / 128, M_ / 128, 3);
    qkv_kernel<<<gq, 256>>>(x, Wq, Wk, Wv);

    // Flash attention (needs >48KB dynamic smem)
    cudaFuncSetAttribute(attn_kernel,
                         cudaFuncAttributeMaxDynamicSharedMemorySize,
                         SMEM_BYTES);
    attn_kernel<<<dim3(S_ / 64, H_, B_), 128, SMEM_BYTES>>>();

    // Output projection + bias
    out_kernel<<<dim3(E_ / 128, M_ / 128, 1), 256>>>(Wo, bo, out);
}

// round 8
// speedup vs baseline: 1.7282x; 1.7282x over previous
#include <cuda_runtime.h>
#include <cfloat>
#include <cmath>
#include <cstdint>

// Problem constants
constexpr int B_ = 2;
constexpr int S_ = 2048;
constexpr int E_ = 2048;
constexpr int H_ = 16;
constexpr int D_ = 128;
constexpr int M_ = B_ * S_;   // 4096 rows for all GEMMs

// Scratch (static device globals: allowed; no dynamic allocation)
__device__ float g_Q[(size_t)B_ * S_ * E_];
__device__ float g_K[(size_t)B_ * S_ * E_];
__device__ float g_V[(size_t)B_ * S_ * E_];
__device__ float g_ctx[(size_t)B_ * S_ * E_];

// ---------------------------------------------------------------------------
// tf32 helpers
// ---------------------------------------------------------------------------
__device__ __forceinline__ uint32_t f2tf32(float x) {
    uint32_t u;
    asm("cvt.rna.tf32.f32 %0, %1;" : "=r"(u) : "f"(x));
    return u;
}

__device__ __forceinline__ void mma_tf32(
    float& c0, float& c1, float& c2, float& c3,
    uint32_t a0, uint32_t a1, uint32_t a2, uint32_t a3,
    uint32_t b0, uint32_t b1)
{
    asm volatile(
        "mma.sync.aligned.m16n8k8.row.col.f32.tf32.tf32.f32 "
        "{%0,%1,%2,%3}, {%4,%5,%6,%7}, {%8,%9}, {%0,%1,%2,%3};\n"
        : "+f"(c0), "+f"(c1), "+f"(c2), "+f"(c3)
        : "r"(a0), "r"(a1), "r"(a2), "r"(a3), "r"(b0), "r"(b1));
}

// ---------------------------------------------------------------------------
// tf32 tensor-core GEMM: C[M,N] = A[M,K] @ W[K,N] (+bias)
// 128x128 CTA tile, BK=32, 8 warps (2x4), warp tile 64x32 as 4x4 m16n8k8.
// A smem [m][k] stride 36 (frag conflict-free), B smem [k][n] stride 136.
// ---------------------------------------------------------------------------
constexpr int AS_STRIDE = 36;    // floats per A smem row (128 rows)
constexpr int BS_STRIDE = 136;   // floats per B smem row (32 rows)

__device__ __forceinline__ void gemm_tf32_128x128(
    const float* __restrict__ A, const float* __restrict__ W,
    float* __restrict__ C, const float* __restrict__ bias)
{
    constexpr int N = E_;
    constexpr int K = E_;
    __shared__ float As[128 * AS_STRIDE];   // 18432 B
    __shared__ float Bs[32 * BS_STRIDE];    // 17408 B

    const int tid  = threadIdx.x;
    const int lane = tid & 31;
    const int warp = tid >> 5;
    const int quad = lane >> 2;   // 0..7
    const int tq   = lane & 3;    // 0..3
    const int wm   = warp >> 2;   // 0..1
    const int wn   = warp & 3;    // 0..3
    const int bm0  = blockIdx.y * 128;
    const int bn0  = blockIdx.x * 128;

    float acc[4][4][4];
#pragma unroll
    for (int mt = 0; mt < 4; mt++)
#pragma unroll
        for (int nt = 0; nt < 4; nt++)
#pragma unroll
            for (int r = 0; r < 4; r++) acc[mt][nt][r] = 0.f;

    for (int kt = 0; kt < K; kt += 32) {
        // --- Load A tile 128x32 (row-major, cvt to tf32 at store) ---
#pragma unroll
        for (int i = 0; i < 4; i++) {
            int idx = tid + i * 256;          // 0..1023
            int r   = idx >> 3;               // 0..127
            int c4  = (idx & 7) << 2;         // 0..28
            float4 v = *(const float4*)(A + (size_t)(bm0 + r) * K + kt + c4);
            float4 o;
            o.x = __uint_as_float(f2tf32(v.x));
            o.y = __uint_as_float(f2tf32(v.y));
            o.z = __uint_as_float(f2tf32(v.z));
            o.w = __uint_as_float(f2tf32(v.w));
            *(float4*)&As[r * AS_STRIDE + c4] = o;
        }
        // --- Load B tile 32x128 ([k][n], cvt to tf32 at store) ---
#pragma unroll
        for (int i = 0; i < 4; i++) {
            int idx = tid + i * 256;          // 0..1023
            int r   = idx >> 5;               // 0..31
            int c4  = (idx & 31) << 2;        // 0..124
            float4 v = *(const float4*)(W + (size_t)(kt + r) * N + bn0 + c4);
            float4 o;
            o.x = __uint_as_float(f2tf32(v.x));
            o.y = __uint_as_float(f2tf32(v.y));
            o.z = __uint_as_float(f2tf32(v.z));
            o.w = __uint_as_float(f2tf32(v.w));
            *(float4*)&Bs[r * BS_STRIDE + c4] = o;
        }
        __syncthreads();

#pragma unroll
        for (int ks = 0; ks < 4; ks++) {
            const int k0 = ks * 8;
            uint32_t a[4][4], b[4][2];
#pragma unroll
            for (int mt = 0; mt < 4; mt++) {
                const int mb = wm * 64 + mt * 16;
                a[mt][0] = __float_as_uint(As[(mb + quad)     * AS_STRIDE + k0 + tq]);
                a[mt][1] = __float_as_uint(As[(mb + 8 + quad) * AS_STRIDE + k0 + tq]);
                a[mt][2] = __float_as_uint(As[(mb + quad)     * AS_STRIDE + k0 + 4 + tq]);
                a[mt][3] = __float_as_uint(As[(mb + 8 + quad) * AS_STRIDE + k0 + 4 + tq]);
            }
#pragma unroll
            for (int nt = 0; nt < 4; nt++) {
                const int nb = wn * 32 + nt * 8;
                b[nt][0] = __float_as_uint(Bs[(k0 + tq)     * BS_STRIDE + nb + quad]);
                b[nt][1] = __float_as_uint(Bs[(k0 + 4 + tq) * BS_STRIDE + nb + quad]);
            }
#pragma unroll
            for (int mt = 0; mt < 4; mt++)
#pragma unroll
                for (int nt = 0; nt < 4; nt++)
                    mma_tf32(acc[mt][nt][0], acc[mt][nt][1],
                             acc[mt][nt][2], acc[mt][nt][3],
                             a[mt][0], a[mt][1], a[mt][2], a[mt][3],
                             b[nt][0], b[nt][1]);
        }
        __syncthreads();
    }

    // --- Epilogue: c0/c1 at (row, 2tq/2tq+1), c2/c3 at (row+8, same) ---
#pragma unroll
    for (int mt = 0; mt < 4; mt++) {
        const int row = bm0 + wm * 64 + mt * 16 + quad;
#pragma unroll
        for (int nt = 0; nt < 4; nt++) {
            const int col = bn0 + wn * 32 + nt * 8 + 2 * tq;
            float bv0 = bias ? bias[col]     : 0.f;
            float bv1 = bias ? bias[col + 1] : 0.f;
            float2 r0, r1;
            r0.x = acc[mt][nt][0] + bv0; r0.y = acc[mt][nt][1] + bv1;
            r1.x = acc[mt][nt][2] + bv0; r1.y = acc[mt][nt][3] + bv1;
            *(float2*)(C + (size_t)row * N + col)       = r0;
            *(float2*)(C + (size_t)(row + 8) * N + col) = r1;
        }
    }
}

__global__ void __launch_bounds__(256, 2) qkv_kernel(
    const float* __restrict__ x,
    const float* __restrict__ Wq,
    const float* __restrict__ Wk,
    const float* __restrict__ Wv)
{
    const float* W = (blockIdx.z == 0) ? Wq : ((blockIdx.z == 1) ? Wk : Wv);
    float* C = (blockIdx.z == 0) ? g_Q : ((blockIdx.z == 1) ? g_K : g_V);
    gemm_tf32_128x128(x, W, C, nullptr);
}

__global__ void __launch_bounds__(256, 2) out_kernel(
    const float* __restrict__ Wo,
    const float* __restrict__ bo,
    float* __restrict__ out)
{
    gemm_tf32_128x128(g_ctx, Wo, out, bo);
}

// ---------------------------------------------------------------------------
// Flash attention: 64x64 tiles, online softmax, causal + ALiBi. (unchanged)
// ---------------------------------------------------------------------------
constexpr int SMEM_FLOATS = 2 * 64 * 129 + 64 * 65 + 3 * 64;  // 20864
constexpr int SMEM_BYTES  = SMEM_FLOATS * 4;                  // 83456

__device__ __forceinline__ void load_tile64x128(
    const float* __restrict__ gp, float* __restrict__ dst, int tid)
{
    for (int idx = tid; idx < 64 * 32; idx += 128) {
        int r  = idx >> 5;
        int c4 = (idx & 31) << 2;
        float4 v = *(const float4*)(gp + (size_t)r * E_ + c4);
        float* d = dst + r * 129 + c4;
        d[0] = v.x; d[1] = v.y; d[2] = v.z; d[3] = v.w;
    }
}

__global__ void __launch_bounds__(128) attn_kernel()
{
    const int tid = threadIdx.x;
    const int qt  = blockIdx.x;
    const int h   = blockIdx.y;
    const int b   = blockIdx.z;
    const int q0  = qt * 64;
    const int tr  = tid >> 3;
    const int tc  = tid & 7;

    extern __shared__ float sm[];
    float* Qs  = sm;                       // [64][129]
    float* KVs = sm + 64 * 129;            // [64][129]
    float* Ssm = sm + 2 * 64 * 129;        // [64][65]
    float* msr = Ssm + 64 * 65;            // [64] running max
    float* lsr = msr + 64;                 // [64] running sum
    float* csr = lsr + 64;                 // [64] correction

    const float slope = exp2f(-0.5f * (float)(h + 1));
    const float inv_s = rsqrtf((float)D_);

    const float* Qp = g_Q + (((size_t)b * S_ + q0) * E_ + (size_t)h * D_);
    load_tile64x128(Qp, Qs, tid);

    if (tid < 64) { msr[tid] = -FLT_MAX; lsr[tid] = 0.f; }

    float o[4][16];
#pragma unroll
    for (int i = 0; i < 4; i++)
#pragma unroll
        for (int c = 0; c < 16; c++) o[i][c] = 0.f;

    __syncthreads();

    for (int kt = 0; kt <= qt; kt++) {
        const int k0 = kt * 64;
        const float* Kp = g_K + (((size_t)b * S_ + k0) * E_ + (size_t)h * D_);
        load_tile64x128(Kp, KVs, tid);
        __syncthreads();

        // --- Phase A: S = Q @ K^T (4x8 microtile) ---
        float acc[4][8];
#pragma unroll
        for (int i = 0; i < 4; i++)
#pragma unroll
            for (int j = 0; j < 8; j++) acc[i][j] = 0.f;

#pragma unroll 4
        for (int kk = 0; kk < 128; kk++) {
            float qv[4], kv[8];
#pragma unroll
            for (int i = 0; i < 4; i++) qv[i] = Qs[(4 * tr + i) * 129 + kk];
#pragma unroll
            for (int j = 0; j < 8; j++) kv[j] = KVs[(8 * tc + j) * 129 + kk];
#pragma unroll
            for (int i = 0; i < 4; i++)
#pragma unroll
                for (int j = 0; j < 8; j++)
                    acc[i][j] += qv[i] * kv[j];
        }

        // mask -> +alibi -> scale (same order as reference)
#pragma unroll
        for (int i = 0; i < 4; i++) {
            const int ig = q0 + 4 * tr + i;
#pragma unroll
            for (int j = 0; j < 8; j++) {
                const int jg = k0 + 8 * tc + j;
                float sv = acc[i][j];
                if (jg > ig) sv = -1e30f;
                sv = (sv + slope * (float)(jg - ig)) * inv_s;
                Ssm[(4 * tr + i) * 65 + 8 * tc + j] = sv;
            }
        }
        __syncthreads();

        // --- Online softmax: 2 threads per row ---
        {
            const int r = tid >> 1, p = tid & 1;
            float* row = Ssm + r * 65 + p * 32;
            float lm = -FLT_MAX;
#pragma unroll 8
            for (int j2 = 0; j2 < 32; j2++) lm = fmaxf(lm, row[j2]);
            lm = fmaxf(lm, __shfl_xor_sync(0xffffffffu, lm, 1));
            const float mo = msr[r];
            const float mn = fmaxf(mo, lm);
            const float cc = __expf(mo - mn);
            float s = 0.f;
#pragma unroll 8
            for (int j2 = 0; j2 < 32; j2++) {
                float pv = __expf(row[j2] - mn);
                row[j2] = pv;
                s += pv;
            }
            s += __shfl_xor_sync(0xffffffffu, s, 1);
            if (!p) {
                msr[r] = mn;
                lsr[r] = cc * lsr[r] + s;
                csr[r] = cc;
            }
        }

        // Load V into KVs
        const float* Vp = g_V + (((size_t)b * S_ + k0) * E_ + (size_t)h * D_);
        load_tile64x128(Vp, KVs, tid);
        __syncthreads();

        // --- Phase B: O = c*O + P @ V (4x16 microtile) ---
        float cr[4];
#pragma unroll
        for (int i = 0; i < 4; i++) cr[i] = csr[4 * tr + i];
#pragma unroll
        for (int i = 0; i < 4; i++)
#pragma unroll
            for (int c = 0; c < 16; c++) o[i][c] *= cr[i];

#pragma unroll 2
        for (int j = 0; j < 64; j++) {
            float pv[4], vv[16];
#pragma unroll
            for (int i = 0; i < 4; i++) pv[i] = Ssm[(4 * tr + i) * 65 + j];
#pragma unroll
            for (int c = 0; c < 16; c++) vv[c] = KVs[j * 129 + tc + 8 * c];
#pragma unroll
            for (int i = 0; i < 4; i++)
#pragma unroll
                for (int c = 0; c < 16; c++)
                    o[i][c] += pv[i] * vv[c];
        }
        __syncthreads();
    }

    // Final normalize and store: ctx[b][q][h][d]
    float* Op = g_ctx + (((size_t)b * S_ + q0) * E_ + (size_t)h * D_);
#pragma unroll
    for (int i = 0; i < 4; i++) {
        const float inv_l = 1.0f / lsr[4 * tr + i];
#pragma unroll
        for (int c = 0; c < 16; c++)
            Op[(size_t)(4 * tr + i) * E_ + tc + 8 * c] = o[i][c] * inv_l;
    }
}

// ---------------------------------------------------------------------------
// Launch
// ---------------------------------------------------------------------------
extern "C" void kernel_launch(void* const* d_in, const int* in_sizes, int n_in,
                              void* d_out, int out_size)
{
    const float* x  = (const float*)d_in[0];
    const float* Wq = (const float*)d_in[1];
    const float* Wk = (const float*)d_in[2];
    const float* Wv = (const float*)d_in[3];
    const float* Wo = (const float*)d_in[4];
    const float* bo = (const float*)d_in[5];
    float* out = (float*)d_out;

    (void)in_sizes; (void)n_in; (void)out_size;

    // Fused QKV projections (tf32 tensor cores)
    dim3 gq(E_ / 128, M_ / 128, 3);
    qkv_kernel<<<gq, 256>>>(x, Wq, Wk, Wv);

    // Flash attention (needs >48KB dynamic smem)
    cudaFuncSetAttribute(attn_kernel,
                         cudaFuncAttributeMaxDynamicSharedMemorySize,
                         SMEM_BYTES);
    attn_kernel<<<dim3(S_ / 64, H_, B_), 128, SMEM_BYTES>>>();

    // Output projection + bias (tf32 tensor cores)
    out_kernel<<<dim3(E_ / 128, M_ / 128, 1), 256>>>(Wo, bo, out);
}

// round 9
// speedup vs baseline: 3.1175x; 1.8038x over previous
#include <cuda_runtime.h>
#include <cfloat>
#include <cmath>
#include <cstdint>

// Problem constants
constexpr int B_ = 2;
constexpr int S_ = 2048;
constexpr int E_ = 2048;
constexpr int H_ = 16;
constexpr int D_ = 128;
constexpr int M_ = B_ * S_;   // 4096 rows for all GEMMs

// Scratch (static device globals: allowed; no dynamic allocation)
__device__ float g_Q[(size_t)B_ * S_ * E_];
__device__ float g_K[(size_t)B_ * S_ * E_];
__device__ float g_V[(size_t)B_ * S_ * E_];
__device__ float g_ctx[(size_t)B_ * S_ * E_];

// ---------------------------------------------------------------------------
// tf32 helpers
// ---------------------------------------------------------------------------
__device__ __forceinline__ uint32_t f2tf32(float x) {
    uint32_t u;
    asm("cvt.rna.tf32.f32 %0, %1;" : "=r"(u) : "f"(x));
    return u;
}

__device__ __forceinline__ void mma_tf32(
    float& c0, float& c1, float& c2, float& c3,
    uint32_t a0, uint32_t a1, uint32_t a2, uint32_t a3,
    uint32_t b0, uint32_t b1)
{
    asm volatile(
        "mma.sync.aligned.m16n8k8.row.col.f32.tf32.tf32.f32 "
        "{%0,%1,%2,%3}, {%4,%5,%6,%7}, {%8,%9}, {%0,%1,%2,%3};\n"
        : "+f"(c0), "+f"(c1), "+f"(c2), "+f"(c3)
        : "r"(a0), "r"(a1), "r"(a2), "r"(a3), "r"(b0), "r"(b1));
}

// ---------------------------------------------------------------------------
// tf32 tensor-core GEMM: C[M,N] = A[M,K] @ W[K,N] (+bias)   (unchanged, proven)
// ---------------------------------------------------------------------------
constexpr int AS_STRIDE = 36;
constexpr int BS_STRIDE = 136;

__device__ __forceinline__ void gemm_tf32_128x128(
    const float* __restrict__ A, const float* __restrict__ W,
    float* __restrict__ C, const float* __restrict__ bias)
{
    constexpr int N = E_;
    constexpr int K = E_;
    __shared__ float As[128 * AS_STRIDE];
    __shared__ float Bs[32 * BS_STRIDE];

    const int tid  = threadIdx.x;
    const int lane = tid & 31;
    const int warp = tid >> 5;
    const int quad = lane >> 2;
    const int tq   = lane & 3;
    const int wm   = warp >> 2;
    const int wn   = warp & 3;
    const int bm0  = blockIdx.y * 128;
    const int bn0  = blockIdx.x * 128;

    float acc[4][4][4];
#pragma unroll
    for (int mt = 0; mt < 4; mt++)
#pragma unroll
        for (int nt = 0; nt < 4; nt++)
#pragma unroll
            for (int r = 0; r < 4; r++) acc[mt][nt][r] = 0.f;

    for (int kt = 0; kt < K; kt += 32) {
#pragma unroll
        for (int i = 0; i < 4; i++) {
            int idx = tid + i * 256;
            int r   = idx >> 3;
            int c4  = (idx & 7) << 2;
            float4 v = *(const float4*)(A + (size_t)(bm0 + r) * K + kt + c4);
            float4 o;
            o.x = __uint_as_float(f2tf32(v.x));
            o.y = __uint_as_float(f2tf32(v.y));
            o.z = __uint_as_float(f2tf32(v.z));
            o.w = __uint_as_float(f2tf32(v.w));
            *(float4*)&As[r * AS_STRIDE + c4] = o;
        }
#pragma unroll
        for (int i = 0; i < 4; i++) {
            int idx = tid + i * 256;
            int r   = idx >> 5;
            int c4  = (idx & 31) << 2;
            float4 v = *(const float4*)(W + (size_t)(kt + r) * N + bn0 + c4);
            float4 o;
            o.x = __uint_as_float(f2tf32(v.x));
            o.y = __uint_as_float(f2tf32(v.y));
            o.z = __uint_as_float(f2tf32(v.z));
            o.w = __uint_as_float(f2tf32(v.w));
            *(float4*)&Bs[r * BS_STRIDE + c4] = o;
        }
        __syncthreads();

#pragma unroll
        for (int ks = 0; ks < 4; ks++) {
            const int k0 = ks * 8;
            uint32_t a[4][4], b[4][2];
#pragma unroll
            for (int mt = 0; mt < 4; mt++) {
                const int mb = wm * 64 + mt * 16;
                a[mt][0] = __float_as_uint(As[(mb + quad)     * AS_STRIDE + k0 + tq]);
                a[mt][1] = __float_as_uint(As[(mb + 8 + quad) * AS_STRIDE + k0 + tq]);
                a[mt][2] = __float_as_uint(As[(mb + quad)     * AS_STRIDE + k0 + 4 + tq]);
                a[mt][3] = __float_as_uint(As[(mb + 8 + quad) * AS_STRIDE + k0 + 4 + tq]);
            }
#pragma unroll
            for (int nt = 0; nt < 4; nt++) {
                const int nb = wn * 32 + nt * 8;
                b[nt][0] = __float_as_uint(Bs[(k0 + tq)     * BS_STRIDE + nb + quad]);
                b[nt][1] = __float_as_uint(Bs[(k0 + 4 + tq) * BS_STRIDE + nb + quad]);
            }
#pragma unroll
            for (int mt = 0; mt < 4; mt++)
#pragma unroll
                for (int nt = 0; nt < 4; nt++)
                    mma_tf32(acc[mt][nt][0], acc[mt][nt][1],
                             acc[mt][nt][2], acc[mt][nt][3],
                             a[mt][0], a[mt][1], a[mt][2], a[mt][3],
                             b[nt][0], b[nt][1]);
        }
        __syncthreads();
    }

#pragma unroll
    for (int mt = 0; mt < 4; mt++) {
        const int row = bm0 + wm * 64 + mt * 16 + quad;
#pragma unroll
        for (int nt = 0; nt < 4; nt++) {
            const int col = bn0 + wn * 32 + nt * 8 + 2 * tq;
            float bv0 = bias ? bias[col]     : 0.f;
            float bv1 = bias ? bias[col + 1] : 0.f;
            float2 r0, r1;
            r0.x = acc[mt][nt][0] + bv0; r0.y = acc[mt][nt][1] + bv1;
            r1.x = acc[mt][nt][2] + bv0; r1.y = acc[mt][nt][3] + bv1;
            *(float2*)(C + (size_t)row * N + col)       = r0;
            *(float2*)(C + (size_t)(row + 8) * N + col) = r1;
        }
    }
}

__global__ void __launch_bounds__(256, 2) qkv_kernel(
    const float* __restrict__ x,
    const float* __restrict__ Wq,
    const float* __restrict__ Wk,
    const float* __restrict__ Wv)
{
    const float* W = (blockIdx.z == 0) ? Wq : ((blockIdx.z == 1) ? Wk : Wv);
    float* C = (blockIdx.z == 0) ? g_Q : ((blockIdx.z == 1) ? g_K : g_V);
    gemm_tf32_128x128(x, W, C, nullptr);
}

__global__ void __launch_bounds__(256, 2) out_kernel(
    const float* __restrict__ Wo,
    const float* __restrict__ bo,
    float* __restrict__ out)
{
    gemm_tf32_128x128(g_ctx, Wo, out, bo);
}

// ---------------------------------------------------------------------------
// Flash attention with tf32 tensor cores.
// 64 q-rows per CTA, 128 threads (4 warps, each owns 16 q-rows).
// Phase A: S(64x64) = Q(64x128) @ K^T via m16n8k8 (K row-major [j][d] == B col-major)
// Phase B: O(64x128) += P(64x64) @ V via m16n8k8 (V transposed in smem [d][j])
// ---------------------------------------------------------------------------
constexpr int QS_ST = 132;   // Q/K smem row stride (frag reads conflict-free)
constexpr int VT_ST = 68;    // Vt / Ssm row stride  (frag reads conflict-free)

constexpr int OFF_Q   = 0;                     // 64*132  = 8448
constexpr int OFF_KV  = OFF_Q + 64 * QS_ST;    // max(64*132, 128*68) = 8704
constexpr int OFF_S   = OFF_KV + 128 * VT_ST;  // 64*68 = 4352
constexpr int OFF_M   = OFF_S + 64 * VT_ST;
constexpr int OFF_L   = OFF_M + 64;
constexpr int OFF_C   = OFF_L + 64;
constexpr int ATT_SMEM_FLOATS = OFF_C + 64;    // 21696
constexpr int ATT_SMEM_BYTES  = ATT_SMEM_FLOATS * 4;  // 86784

// Load 64x128 tile row-major into smem (stride QS_ST), cvt to tf32.
__device__ __forceinline__ void load_qk_tile(
    const float* __restrict__ gp, float* __restrict__ dst, int tid)
{
#pragma unroll
    for (int it = 0; it < 16; it++) {
        int idx = tid + it * 128;
        int r   = idx >> 5;
        int c4  = (idx & 31) << 2;
        float4 v = *(const float4*)(gp + (size_t)r * E_ + c4);
        float4 o;
        o.x = __uint_as_float(f2tf32(v.x));
        o.y = __uint_as_float(f2tf32(v.y));
        o.z = __uint_as_float(f2tf32(v.z));
        o.w = __uint_as_float(f2tf32(v.w));
        *(float4*)&dst[r * QS_ST + c4] = o;
    }
}

// Load 64x128 V tile TRANSPOSED into smem as Vt[128][VT_ST], cvt to tf32.
// Gmem: lanes read consecutive d (coalesced). Smem: float4 along j
// (conflict-free STS.128: bank-quad = lane mod 8).
__device__ __forceinline__ void load_v_tileT(
    const float* __restrict__ gp, float* __restrict__ dst, int tid)
{
#pragma unroll
    for (int it = 0; it < 16; it++) {
        int idx = tid + it * 128;
        int c   = idx & 127;        // d index
        int j0  = (idx >> 7) * 4;   // j group
        float4 o;
        o.x = __uint_as_float(f2tf32(gp[(size_t)(j0 + 0) * E_ + c]));
        o.y = __uint_as_float(f2tf32(gp[(size_t)(j0 + 1) * E_ + c]));
        o.z = __uint_as_float(f2tf32(gp[(size_t)(j0 + 2) * E_ + c]));
        o.w = __uint_as_float(f2tf32(gp[(size_t)(j0 + 3) * E_ + c]));
        *(float4*)&dst[c * VT_ST + j0] = o;
    }
}

__global__ void __launch_bounds__(128, 2) attn_kernel()
{
    const int tid  = threadIdx.x;
    const int lane = tid & 31;
    const int warp = tid >> 5;
    const int quad = lane >> 2;   // 0..7
    const int tq   = lane & 3;    // 0..3
    const int mb   = warp * 16;   // warp's q-row base within tile

    const int qt = (gridDim.x - 1) - blockIdx.x;   // heavy tiles first
    const int h  = blockIdx.y;
    const int b  = blockIdx.z;
    const int q0 = qt * 64;

    extern __shared__ float sm[];
    float* Qs  = sm + OFF_Q;
    float* KVs = sm + OFF_KV;   // K tile [64][132] then Vt [128][68]
    float* Ssm = sm + OFF_S;    // [64][68]
    float* msr = sm + OFF_M;
    float* lsr = sm + OFF_L;
    float* csr = sm + OFF_C;

    const float slope = exp2f(-0.5f * (float)(h + 1));
    const float inv_s = rsqrtf((float)D_);

    const float* Qp = g_Q + (((size_t)b * S_ + q0) * E_ + (size_t)h * D_);
    load_qk_tile(Qp, Qs, tid);
    if (tid < 64) { msr[tid] = -FLT_MAX; lsr[tid] = 0.f; }

    // O accumulators: 16 n-tiles (d) x 4 regs
    float oc[16][4];
#pragma unroll
    for (int nt = 0; nt < 16; nt++)
#pragma unroll
        for (int r = 0; r < 4; r++) oc[nt][r] = 0.f;

    __syncthreads();

    for (int kt = 0; kt <= qt; kt++) {
        const int k0g = kt * 64;
        const float* Kp = g_K + (((size_t)b * S_ + k0g) * E_ + (size_t)h * D_);
        load_qk_tile(Kp, KVs, tid);
        __syncthreads();

        // --- Phase A: S(16x64 per warp) = Q @ K^T ---
        float sc[8][4];
#pragma unroll
        for (int nt = 0; nt < 8; nt++)
#pragma unroll
            for (int r = 0; r < 4; r++) sc[nt][r] = 0.f;

#pragma unroll
        for (int ks = 0; ks < 16; ks++) {
            const int k0 = ks * 8;
            uint32_t a[4], bb[8][2];
            a[0] = __float_as_uint(Qs[(mb + quad)     * QS_ST + k0 + tq]);
            a[1] = __float_as_uint(Qs[(mb + 8 + quad) * QS_ST + k0 + tq]);
            a[2] = __float_as_uint(Qs[(mb + quad)     * QS_ST + k0 + 4 + tq]);
            a[3] = __float_as_uint(Qs[(mb + 8 + quad) * QS_ST + k0 + 4 + tq]);
#pragma unroll
            for (int nt = 0; nt < 8; nt++) {
                const int nb = nt * 8;
                bb[nt][0] = __float_as_uint(KVs[(nb + quad) * QS_ST + k0 + tq]);
                bb[nt][1] = __float_as_uint(KVs[(nb + quad) * QS_ST + k0 + 4 + tq]);
            }
#pragma unroll
            for (int nt = 0; nt < 8; nt++)
                mma_tf32(sc[nt][0], sc[nt][1], sc[nt][2], sc[nt][3],
                         a[0], a[1], a[2], a[3], bb[nt][0], bb[nt][1]);
        }

        // mask -> +alibi -> scale (reference order), write to Ssm
        const int ig0 = q0 + mb + quad;
        const int ig1 = ig0 + 8;
#pragma unroll
        for (int nt = 0; nt < 8; nt++) {
            const int col = nt * 8 + 2 * tq;
            const int jg0 = k0g + col;
#pragma unroll
            for (int e = 0; e < 2; e++) {
                const int jg = jg0 + e;
                float s0 = sc[nt][e];
                float s1 = sc[nt][2 + e];
                if (jg > ig0) s0 = -1e30f;
                if (jg > ig1) s1 = -1e30f;
                s0 = (s0 + slope * (float)(jg - ig0)) * inv_s;
                s1 = (s1 + slope * (float)(jg - ig1)) * inv_s;
                Ssm[(mb + quad)     * VT_ST + col + e] = s0;
                Ssm[(mb + 8 + quad) * VT_ST + col + e] = s1;
            }
        }
        __syncwarp();

        // --- Online softmax: 2 threads per row (row = tid>>1, same warp) ---
        {
            const int r = tid >> 1, p = tid & 1;
            float* row = Ssm + r * VT_ST + p * 32;
            float lm = -FLT_MAX;
#pragma unroll 8
            for (int j2 = 0; j2 < 32; j2++) lm = fmaxf(lm, row[j2]);
            lm = fmaxf(lm, __shfl_xor_sync(0xffffffffu, lm, 1));
            const float mo = msr[r];
            const float mn = fmaxf(mo, lm);
            const float cc = __expf(mo - mn);
            float s = 0.f;
#pragma unroll 8
            for (int j2 = 0; j2 < 32; j2++) {
                float pv = __expf(row[j2] - mn);
                pv = __uint_as_float(f2tf32(pv));   // round to what P@V consumes
                row[j2] = pv;
                s += pv;
            }
            s += __shfl_xor_sync(0xffffffffu, s, 1);
            if (!p) {
                msr[r] = mn;
                lsr[r] = cc * lsr[r] + s;
                csr[r] = cc;
            }
        }
        __syncthreads();   // all phase-A KVs reads done; Ssm/stats published

        // Load V transposed into KVs
        const float* Vp = g_V + (((size_t)b * S_ + k0g) * E_ + (size_t)h * D_);
        load_v_tileT(Vp, KVs, tid);
        __syncthreads();

        // --- Phase B: O = c*O + P @ V ---
        const float cr0 = csr[mb + quad];
        const float cr1 = csr[mb + 8 + quad];
#pragma unroll
        for (int nt = 0; nt < 16; nt++) {
            oc[nt][0] *= cr0; oc[nt][1] *= cr0;
            oc[nt][2] *= cr1; oc[nt][3] *= cr1;
        }

#pragma unroll
        for (int kk = 0; kk < 8; kk++) {
            const int k0 = kk * 8;
            uint32_t a[4];
            a[0] = __float_as_uint(Ssm[(mb + quad)     * VT_ST + k0 + tq]);
            a[1] = __float_as_uint(Ssm[(mb + 8 + quad) * VT_ST + k0 + tq]);
            a[2] = __float_as_uint(Ssm[(mb + quad)     * VT_ST + k0 + 4 + tq]);
            a[3] = __float_as_uint(Ssm[(mb + 8 + quad) * VT_ST + k0 + 4 + tq]);
#pragma unroll
            for (int nt = 0; nt < 16; nt++) {
                const int nb = nt * 8;
                uint32_t b0 = __float_as_uint(KVs[(nb + quad) * VT_ST + k0 + tq]);
                uint32_t b1 = __float_as_uint(KVs[(nb + quad) * VT_ST + k0 + 4 + tq]);
                mma_tf32(oc[nt][0], oc[nt][1], oc[nt][2], oc[nt][3],
                         a[0], a[1], a[2], a[3], b0, b1);
            }
        }
        __syncthreads();   // protect KVs/Ssm before next iteration
    }

    // Final normalize and store: ctx[b][q][h][d]
    const float inv0 = 1.0f / lsr[mb + quad];
    const float inv1 = 1.0f / lsr[mb + 8 + quad];
    float* Op = g_ctx + (((size_t)b * S_ + q0) * E_ + (size_t)h * D_);
    const size_t r0 = (size_t)(mb + quad) * E_;
    const size_t r1 = (size_t)(mb + 8 + quad) * E_;
#pragma unroll
    for (int nt = 0; nt < 16; nt++) {
        const int col = nt * 8 + 2 * tq;
        float2 v0, v1;
        v0.x = oc[nt][0] * inv0; v0.y = oc[nt][1] * inv0;
        v1.x = oc[nt][2] * inv1; v1.y = oc[nt][3] * inv1;
        *(float2*)(Op + r0 + col) = v0;
        *(float2*)(Op + r1 + col) = v1;
    }
}

// ---------------------------------------------------------------------------
// Launch
// ---------------------------------------------------------------------------
extern "C" void kernel_launch(void* const* d_in, const int* in_sizes, int n_in,
                              void* d_out, int out_size)
{
    const float* x  = (const float*)d_in[0];
    const float* Wq = (const float*)d_in[1];
    const float* Wk = (const float*)d_in[2];
    const float* Wv = (const float*)d_in[3];
    const float* Wo = (const float*)d_in[4];
    const float* bo = (const float*)d_in[5];
    float* out = (float*)d_out;

    (void)in_sizes; (void)n_in; (void)out_size;

    // Fused QKV projections (tf32 tensor cores)
    dim3 gq(E_ / 128, M_ / 128, 3);
    qkv_kernel<<<gq, 256>>>(x, Wq, Wk, Wv);

    // Flash attention (tf32 tensor cores; >48KB dynamic smem)
    cudaFuncSetAttribute(attn_kernel,
                         cudaFuncAttributeMaxDynamicSharedMemorySize,
                         ATT_SMEM_BYTES);
    attn_kernel<<<dim3(S_ / 64, H_, B_), 128, ATT_SMEM_BYTES>>>();

    // Output projection + bias (tf32 tensor cores)
    out_kernel<<<dim3(E_ / 128, M_ / 128, 1), 256>>>(Wo, bo, out);
}

// round 10
// speedup vs baseline: 3.5021x; 1.1234x over previous
#include <cuda_runtime.h>
#include <cfloat>
#include <cmath>
#include <cstdint>

// Problem constants
constexpr int B_ = 2;
constexpr int S_ = 2048;
constexpr int E_ = 2048;
constexpr int H_ = 16;
constexpr int D_ = 128;
constexpr int M_ = B_ * S_;   // 4096 rows for all GEMMs

// Scratch (static device globals: allowed; no dynamic allocation)
__device__ float g_Q[(size_t)B_ * S_ * E_];
__device__ float g_K[(size_t)B_ * S_ * E_];
__device__ float g_V[(size_t)B_ * S_ * E_];
__device__ float g_ctx[(size_t)B_ * S_ * E_];
// tf32-pre-rounded copies of GEMM inputs (lets mainloop use raw cp.async)
__device__ float g_X [(size_t)M_ * E_];
__device__ float g_Wq[(size_t)E_ * E_];
__device__ float g_Wk[(size_t)E_ * E_];
__device__ float g_Wv[(size_t)E_ * E_];
__device__ float g_Wo[(size_t)E_ * E_];

// ---------------------------------------------------------------------------
// tf32 + cp.async helpers
// ---------------------------------------------------------------------------
__device__ __forceinline__ uint32_t f2tf32(float x) {
    uint32_t u;
    asm("cvt.rna.tf32.f32 %0, %1;" : "=r"(u) : "f"(x));
    return u;
}
__device__ __forceinline__ float f2tf32f(float x) {
    return __uint_as_float(f2tf32(x));
}

__device__ __forceinline__ void mma_tf32(
    float& c0, float& c1, float& c2, float& c3,
    uint32_t a0, uint32_t a1, uint32_t a2, uint32_t a3,
    uint32_t b0, uint32_t b1)
{
    asm volatile(
        "mma.sync.aligned.m16n8k8.row.col.f32.tf32.tf32.f32 "
        "{%0,%1,%2,%3}, {%4,%5,%6,%7}, {%8,%9}, {%0,%1,%2,%3};\n"
        : "+f"(c0), "+f"(c1), "+f"(c2), "+f"(c3)
        : "r"(a0), "r"(a1), "r"(a2), "r"(a3), "r"(b0), "r"(b1));
}

__device__ __forceinline__ void cp_async16(uint32_t dst_smem, const void* src) {
    asm volatile("cp.async.cg.shared.global [%0], [%1], 16;\n"
                 :: "r"(dst_smem), "l"(src));
}
__device__ __forceinline__ void cp_commit() {
    asm volatile("cp.async.commit_group;\n");
}
template <int N>
__device__ __forceinline__ void cp_wait() {
    asm volatile("cp.async.wait_group %0;\n" :: "n"(N));
}

// ---------------------------------------------------------------------------
// Pre-pass: round x + weights to tf32 (elementwise, memory-bound)
// z = 0: x -> g_X ; z = 1..4: Wq/Wk/Wv/Wo -> g_Wq/..
// ---------------------------------------------------------------------------
__global__ void __launch_bounds__(256) round_tf32_kernel(
    const float* __restrict__ x,  const float* __restrict__ wq,
    const float* __restrict__ wk, const float* __restrict__ wv,
    const float* __restrict__ wo)
{
    const float* src; float* dst; size_t n4;
    switch (blockIdx.z) {
        case 0: src = x;  dst = g_X;  n4 = (size_t)M_ * E_ / 4; break;
        case 1: src = wq; dst = g_Wq; n4 = (size_t)E_ * E_ / 4; break;
        case 2: src = wk; dst = g_Wk; n4 = (size_t)E_ * E_ / 4; break;
        case 3: src = wv; dst = g_Wv; n4 = (size_t)E_ * E_ / 4; break;
        default: src = wo; dst = g_Wo; n4 = (size_t)E_ * E_ / 4; break;
    }
    const size_t stride = (size_t)gridDim.x * blockDim.x;
    for (size_t i = (size_t)blockIdx.x * blockDim.x + threadIdx.x; i < n4;
         i += stride) {
        float4 v = ((const float4*)src)[i];
        v.x = f2tf32f(v.x); v.y = f2tf32f(v.y);
        v.z = f2tf32f(v.z); v.w = f2tf32f(v.w);
        ((float4*)dst)[i] = v;
    }
}

// ---------------------------------------------------------------------------
// tf32 tensor-core GEMM with cp.async double buffering.
// C[M,N] = A[M,K] @ W[K,N] (+bias); A,W must be pre-rounded to tf32.
// 128x128 CTA tile, BK=32, 8 warps, warp tile 64x32 as 4x4 m16n8k8.
// ---------------------------------------------------------------------------
constexpr int AS_STRIDE = 36;                 // A smem row stride (floats)
constexpr int BS_STRIDE = 136;                // B smem row stride (floats)
constexpr int A_BUF = 128 * AS_STRIDE;        // 4608 floats per stage
constexpr int B_BUF = 32 * BS_STRIDE;         // 4352 floats per stage
constexpr int GEMM_SMEM_FLOATS = 2 * (A_BUF + B_BUF);           // 17920
constexpr int GEMM_SMEM_BYTES  = GEMM_SMEM_FLOATS * 4;          // 71680

__device__ __forceinline__ void gemm_tf32_pipe(
    const float* __restrict__ A, const float* __restrict__ W,
    float* __restrict__ C, const float* __restrict__ bias)
{
    constexpr int N = E_;
    constexpr int K = E_;
    constexpr int NT = K / 32;

    extern __shared__ float sm[];
    float* As = sm;                 // [2][128*AS_STRIDE]
    float* Bs = sm + 2 * A_BUF;     // [2][32*BS_STRIDE]

    const int tid  = threadIdx.x;
    const int lane = tid & 31;
    const int warp = tid >> 5;
    const int quad = lane >> 2;
    const int tq   = lane & 3;
    const int wm   = warp >> 2;
    const int wn   = warp & 3;
    const int bm0  = blockIdx.y * 128;
    const int bn0  = blockIdx.x * 128;

    // per-thread load coordinates (fixed across tiles)
    const int ar = tid >> 3;                 // A row   0..31 (+32*i)
    const int ac = (tid & 7) << 2;           // A col4
    const int br = tid >> 5;                 // B row   0..7  (+8*i)
    const int bc = (tid & 31) << 2;          // B col4

    float acc[4][4][4];
#pragma unroll
    for (int mt = 0; mt < 4; mt++)
#pragma unroll
        for (int nt = 0; nt < 4; nt++)
#pragma unroll
            for (int r = 0; r < 4; r++) acc[mt][nt][r] = 0.f;

    // --- async tile loader ---
    auto issue = [&](int kt, int buf) {
        const float* Ag = A + (size_t)bm0 * K + kt * 32;
#pragma unroll
        for (int i = 0; i < 4; i++) {
            int r = ar + i * 32;
            uint32_t d = (uint32_t)__cvta_generic_to_shared(
                &As[buf * A_BUF + r * AS_STRIDE + ac]);
            cp_async16(d, Ag + (size_t)r * K + ac);
        }
        const float* Wg = W + (size_t)(kt * 32) * N + bn0;
#pragma unroll
        for (int i = 0; i < 4; i++) {
            int r = br + i * 8;
            uint32_t d = (uint32_t)__cvta_generic_to_shared(
                &Bs[buf * B_BUF + r * BS_STRIDE + bc]);
            cp_async16(d, Wg + (size_t)r * N + bc);
        }
        cp_commit();
    };

    issue(0, 0);

    for (int t = 0; t < NT; t++) {
        const int buf = t & 1;
        if (t + 1 < NT) {
            issue(t + 1, buf ^ 1);   // prefetch next tile into other buffer
            cp_wait<1>();            // tile t has landed
        } else {
            cp_wait<0>();
        }
        __syncthreads();

        const float* Ab = &As[buf * A_BUF];
        const float* Bb = &Bs[buf * B_BUF];

#pragma unroll
        for (int ks = 0; ks < 4; ks++) {
            const int k0 = ks * 8;
            uint32_t a[4][4], b[4][2];
#pragma unroll
            for (int mt = 0; mt < 4; mt++) {
                const int mb = wm * 64 + mt * 16;
                a[mt][0] = __float_as_uint(Ab[(mb + quad)     * AS_STRIDE + k0 + tq]);
                a[mt][1] = __float_as_uint(Ab[(mb + 8 + quad) * AS_STRIDE + k0 + tq]);
                a[mt][2] = __float_as_uint(Ab[(mb + quad)     * AS_STRIDE + k0 + 4 + tq]);
                a[mt][3] = __float_as_uint(Ab[(mb + 8 + quad) * AS_STRIDE + k0 + 4 + tq]);
            }
#pragma unroll
            for (int nt = 0; nt < 4; nt++) {
                const int nb = wn * 32 + nt * 8;
                b[nt][0] = __float_as_uint(Bb[(k0 + tq)     * BS_STRIDE + nb + quad]);
                b[nt][1] = __float_as_uint(Bb[(k0 + 4 + tq) * BS_STRIDE + nb + quad]);
            }
#pragma unroll
            for (int mt = 0; mt < 4; mt++)
#pragma unroll
                for (int nt = 0; nt < 4; nt++)
                    mma_tf32(acc[mt][nt][0], acc[mt][nt][1],
                             acc[mt][nt][2], acc[mt][nt][3],
                             a[mt][0], a[mt][1], a[mt][2], a[mt][3],
                             b[nt][0], b[nt][1]);
        }
        __syncthreads();   // MMA reads done before buf is refilled at t+2
    }

    // --- Epilogue ---
#pragma unroll
    for (int mt = 0; mt < 4; mt++) {
        const int row = bm0 + wm * 64 + mt * 16 + quad;
#pragma unroll
        for (int nt = 0; nt < 4; nt++) {
            const int col = bn0 + wn * 32 + nt * 8 + 2 * tq;
            float bv0 = bias ? bias[col]     : 0.f;
            float bv1 = bias ? bias[col + 1] : 0.f;
            float2 r0, r1;
            r0.x = acc[mt][nt][0] + bv0; r0.y = acc[mt][nt][1] + bv1;
            r1.x = acc[mt][nt][2] + bv0; r1.y = acc[mt][nt][3] + bv1;
            *(float2*)(C + (size_t)row * N + col)       = r0;
            *(float2*)(C + (size_t)(row + 8) * N + col) = r1;
        }
    }
}

__global__ void __launch_bounds__(256, 2) qkv_kernel()
{
    const float* W = (blockIdx.z == 0) ? g_Wq : ((blockIdx.z == 1) ? g_Wk : g_Wv);
    float* C = (blockIdx.z == 0) ? g_Q : ((blockIdx.z == 1) ? g_K : g_V);
    gemm_tf32_pipe(g_X, W, C, nullptr);
}

__global__ void __launch_bounds__(256, 2) out_kernel(
    const float* __restrict__ bo, float* __restrict__ out)
{
    // g_ctx is written tf32-rounded by attn epilogue; g_Wo pre-rounded.
    gemm_tf32_pipe(g_ctx, g_Wo, out, bo);
}

// ---------------------------------------------------------------------------
// Flash attention with tf32 tensor cores (unchanged except tf32-rounded
// ctx stores in the epilogue, feeding the cvt-free out GEMM).
// ---------------------------------------------------------------------------
constexpr int QS_ST = 132;
constexpr int VT_ST = 68;

constexpr int OFF_Q   = 0;
constexpr int OFF_KV  = OFF_Q + 64 * QS_ST;
constexpr int OFF_S   = OFF_KV + 128 * VT_ST;
constexpr int OFF_M   = OFF_S + 64 * VT_ST;
constexpr int OFF_L   = OFF_M + 64;
constexpr int OFF_C   = OFF_L + 64;
constexpr int ATT_SMEM_FLOATS = OFF_C + 64;
constexpr int ATT_SMEM_BYTES  = ATT_SMEM_FLOATS * 4;  // 86784

__device__ __forceinline__ void load_qk_tile(
    const float* __restrict__ gp, float* __restrict__ dst, int tid)
{
#pragma unroll
    for (int it = 0; it < 16; it++) {
        int idx = tid + it * 128;
        int r   = idx >> 5;
        int c4  = (idx & 31) << 2;
        float4 v = *(const float4*)(gp + (size_t)r * E_ + c4);
        float4 o;
        o.x = f2tf32f(v.x); o.y = f2tf32f(v.y);
        o.z = f2tf32f(v.z); o.w = f2tf32f(v.w);
        *(float4*)&dst[r * QS_ST + c4] = o;
    }
}

__device__ __forceinline__ void load_v_tileT(
    const float* __restrict__ gp, float* __restrict__ dst, int tid)
{
#pragma unroll
    for (int it = 0; it < 16; it++) {
        int idx = tid + it * 128;
        int c   = idx & 127;
        int j0  = (idx >> 7) * 4;
        float4 o;
        o.x = f2tf32f(gp[(size_t)(j0 + 0) * E_ + c]);
        o.y = f2tf32f(gp[(size_t)(j0 + 1) * E_ + c]);
        o.z = f2tf32f(gp[(size_t)(j0 + 2) * E_ + c]);
        o.w = f2tf32f(gp[(size_t)(j0 + 3) * E_ + c]);
        *(float4*)&dst[c * VT_ST + j0] = o;
    }
}

__global__ void __launch_bounds__(128, 2) attn_kernel()
{
    const int tid  = threadIdx.x;
    const int lane = tid & 31;
    const int warp = tid >> 5;
    const int quad = lane >> 2;
    const int tq   = lane & 3;
    const int mb   = warp * 16;

    const int qt = (gridDim.x - 1) - blockIdx.x;   // heavy tiles first
    const int h  = blockIdx.y;
    const int b  = blockIdx.z;
    const int q0 = qt * 64;

    extern __shared__ float sm[];
    float* Qs  = sm + OFF_Q;
    float* KVs = sm + OFF_KV;
    float* Ssm = sm + OFF_S;
    float* msr = sm + OFF_M;
    float* lsr = sm + OFF_L;
    float* csr = sm + OFF_C;

    const float slope = exp2f(-0.5f * (float)(h + 1));
    const float inv_s = rsqrtf((float)D_);

    const float* Qp = g_Q + (((size_t)b * S_ + q0) * E_ + (size_t)h * D_);
    load_qk_tile(Qp, Qs, tid);
    if (tid < 64) { msr[tid] = -FLT_MAX; lsr[tid] = 0.f; }

    float oc[16][4];
#pragma unroll
    for (int nt = 0; nt < 16; nt++)
#pragma unroll
        for (int r = 0; r < 4; r++) oc[nt][r] = 0.f;

    __syncthreads();

    for (int kt = 0; kt <= qt; kt++) {
        const int k0g = kt * 64;
        const float* Kp = g_K + (((size_t)b * S_ + k0g) * E_ + (size_t)h * D_);
        load_qk_tile(Kp, KVs, tid);
        __syncthreads();

        // --- Phase A: S(16x64 per warp) = Q @ K^T ---
        float sc[8][4];
#pragma unroll
        for (int nt = 0; nt < 8; nt++)
#pragma unroll
            for (int r = 0; r < 4; r++) sc[nt][r] = 0.f;

#pragma unroll
        for (int ks = 0; ks < 16; ks++) {
            const int k0 = ks * 8;
            uint32_t a[4], bb[8][2];
            a[0] = __float_as_uint(Qs[(mb + quad)     * QS_ST + k0 + tq]);
            a[1] = __float_as_uint(Qs[(mb + 8 + quad) * QS_ST + k0 + tq]);
            a[2] = __float_as_uint(Qs[(mb + quad)     * QS_ST + k0 + 4 + tq]);
            a[3] = __float_as_uint(Qs[(mb + 8 + quad) * QS_ST + k0 + 4 + tq]);
#pragma unroll
            for (int nt = 0; nt < 8; nt++) {
                const int nb = nt * 8;
                bb[nt][0] = __float_as_uint(KVs[(nb + quad) * QS_ST + k0 + tq]);
                bb[nt][1] = __float_as_uint(KVs[(nb + quad) * QS_ST + k0 + 4 + tq]);
            }
#pragma unroll
            for (int nt = 0; nt < 8; nt++)
                mma_tf32(sc[nt][0], sc[nt][1], sc[nt][2], sc[nt][3],
                         a[0], a[1], a[2], a[3], bb[nt][0], bb[nt][1]);
        }

        // mask -> +alibi -> scale (reference order)
        const int ig0 = q0 + mb + quad;
        const int ig1 = ig0 + 8;
#pragma unroll
        for (int nt = 0; nt < 8; nt++) {
            const int col = nt * 8 + 2 * tq;
            const int jg0 = k0g + col;
#pragma unroll
            for (int e = 0; e < 2; e++) {
                const int jg = jg0 + e;
                float s0 = sc[nt][e];
                float s1 = sc[nt][2 + e];
                if (jg > ig0) s0 = -1e30f;
                if (jg > ig1) s1 = -1e30f;
                s0 = (s0 + slope * (float)(jg - ig0)) * inv_s;
                s1 = (s1 + slope * (float)(jg - ig1)) * inv_s;
                Ssm[(mb + quad)     * VT_ST + col + e] = s0;
                Ssm[(mb + 8 + quad) * VT_ST + col + e] = s1;
            }
        }
        __syncwarp();

        // --- Online softmax: 2 threads per row ---
        {
            const int r = tid >> 1, p = tid & 1;
            float* row = Ssm + r * VT_ST + p * 32;
            float lm = -FLT_MAX;
#pragma unroll 8
            for (int j2 = 0; j2 < 32; j2++) lm = fmaxf(lm, row[j2]);
            lm = fmaxf(lm, __shfl_xor_sync(0xffffffffu, lm, 1));
            const float mo = msr[r];
            const float mn = fmaxf(mo, lm);
            const float cc = __expf(mo - mn);
            float s = 0.f;
#pragma unroll 8
            for (int j2 = 0; j2 < 32; j2++) {
                float pv = __expf(row[j2] - mn);
                pv = f2tf32f(pv);
                row[j2] = pv;
                s += pv;
            }
            s += __shfl_xor_sync(0xffffffffu, s, 1);
            if (!p) {
                msr[r] = mn;
                lsr[r] = cc * lsr[r] + s;
                csr[r] = cc;
            }
        }
        __syncthreads();

        // Load V transposed
        const float* Vp = g_V + (((size_t)b * S_ + k0g) * E_ + (size_t)h * D_);
        load_v_tileT(Vp, KVs, tid);
        __syncthreads();

        // --- Phase B: O = c*O + P @ V ---
        const float cr0 = csr[mb + quad];
        const float cr1 = csr[mb + 8 + quad];
#pragma unroll
        for (int nt = 0; nt < 16; nt++) {
            oc[nt][0] *= cr0; oc[nt][1] *= cr0;
            oc[nt][2] *= cr1; oc[nt][3] *= cr1;
        }

#pragma unroll
        for (int kk = 0; kk < 8; kk++) {
            const int k0 = kk * 8;
            uint32_t a[4];
            a[0] = __float_as_uint(Ssm[(mb + quad)     * VT_ST + k0 + tq]);
            a[1] = __float_as_uint(Ssm[(mb + 8 + quad) * VT_ST + k0 + tq]);
            a[2] = __float_as_uint(Ssm[(mb + quad)     * VT_ST + k0 + 4 + tq]);
            a[3] = __float_as_uint(Ssm[(mb + 8 + quad) * VT_ST + k0 + 4 + tq]);
#pragma unroll
            for (int nt = 0; nt < 16; nt++) {
                const int nb = nt * 8;
                uint32_t b0 = __float_as_uint(KVs[(nb + quad) * VT_ST + k0 + tq]);
                uint32_t b1 = __float_as_uint(KVs[(nb + quad) * VT_ST + k0 + 4 + tq]);
                mma_tf32(oc[nt][0], oc[nt][1], oc[nt][2], oc[nt][3],
                         a[0], a[1], a[2], a[3], b0, b1);
            }
        }
        __syncthreads();
    }

    // Final normalize; store tf32-rounded ctx (consumed raw by out GEMM)
    const float inv0 = 1.0f / lsr[mb + quad];
    const float inv1 = 1.0f / lsr[mb + 8 + quad];
    float* Op = g_ctx + (((size_t)b * S_ + q0) * E_ + (size_t)h * D_);
    const size_t r0 = (size_t)(mb + quad) * E_;
    const size_t r1 = (size_t)(mb + 8 + quad) * E_;
#pragma unroll
    for (int nt = 0; nt < 16; nt++) {
        const int col = nt * 8 + 2 * tq;
        float2 v0, v1;
        v0.x = f2tf32f(oc[nt][0] * inv0); v0.y = f2tf32f(oc[nt][1] * inv0);
        v1.x = f2tf32f(oc[nt][2] * inv1); v1.y = f2tf32f(oc[nt][3] * inv1);
        *(float2*)(Op + r0 + col) = v0;
        *(float2*)(Op + r1 + col) = v1;
    }
}

// ---------------------------------------------------------------------------
// Launch
// ---------------------------------------------------------------------------
extern "C" void kernel_launch(void* const* d_in, const int* in_sizes, int n_in,
                              void* d_out, int out_size)
{
    const float* x  = (const float*)d_in[0];
    const float* Wq = (const float*)d_in[1];
    const float* Wk = (const float*)d_in[2];
    const float* Wv = (const float*)d_in[3];
    const float* Wo = (const float*)d_in[4];
    const float* bo = (const float*)d_in[5];
    float* out = (float*)d_out;

    (void)in_sizes; (void)n_in; (void)out_size;

    // Pre-round GEMM inputs to tf32 (memory-bound, ~40us)
    round_tf32_kernel<<<dim3(1024, 1, 5), 256>>>(x, Wq, Wk, Wv, Wo);

    // smem attributes (>48KB dynamic)
    cudaFuncSetAttribute(qkv_kernel,
                         cudaFuncAttributeMaxDynamicSharedMemorySize,
                         GEMM_SMEM_BYTES);
    cudaFuncSetAttribute(out_kernel,
                         cudaFuncAttributeMaxDynamicSharedMemorySize,
                         GEMM_SMEM_BYTES);
    cudaFuncSetAttribute(attn_kernel,
                         cudaFuncAttributeMaxDynamicSharedMemorySize,
                         ATT_SMEM_BYTES);

    // Fused QKV projections (pipelined tf32 tensor cores)
    dim3 gq(E_ / 128, M_ / 128, 3);
    qkv_kernel<<<gq, 256, GEMM_SMEM_BYTES>>>();

    // Flash attention (tf32 tensor cores)
    attn_kernel<<<dim3(S_ / 64, H_, B_), 128, ATT_SMEM_BYTES>>>();

    // Output projection + bias (pipelined tf32 tensor cores)
    out_kernel<<<dim3(E_ / 128, M_ / 128, 1), 256, GEMM_SMEM_BYTES>>>(bo, out);
}